// round 1
// baseline (speedup 1.0000x reference)
#include <cuda_runtime.h>
#include <math.h>
#include <stdint.h>

#define NN 50000

// ---------------- scratch (device globals; no allocations allowed) ----------
__device__ float g_feat[NN * 768];   // per-node [Aq|Bq|Ak|Bk|Av|Bv], stride 6*O (max 768)
__device__ float g_x0[NN * 128];     // relu(layer0 out) -- needed for residual
__device__ float g_h1[NN * 64];      // relu(layer1 out)
__device__ float g_acc[NN * 128];    // edge-aggregation accumulator
__device__ float g_cnt[NN];          // edge count per dst
__device__ float g_wcat[128 * 768];  // concatenated transformed weights (C x 6O)
__device__ float g_bcat[768];        // concatenated bias (bias only on A columns)

// ---------------- build W_cat = [Wtop-Wbot | Wbot] x {q,k,v} ----------------
__global__ void build_wcat(const float* __restrict__ wq, const float* __restrict__ wk,
                           const float* __restrict__ wv, const float* __restrict__ bq,
                           const float* __restrict__ bk, const float* __restrict__ bv,
                           int C, int O) {
    int M = 6 * O;
    int idx = blockIdx.x * blockDim.x + threadIdx.x;
    if (idx < C * M) {
        int c = idx / M, col = idx % M;
        int grp = col / O, j = col % O;
        const float* w = (grp < 2) ? wq : (grp < 4 ? wk : wv);
        float top = w[c * O + j];
        float bot = w[(C + c) * O + j];
        g_wcat[idx] = (grp & 1) ? bot : (top - bot);
    }
    if (idx < M) {
        int grp = idx / O, j = idx % O;
        const float* b = (grp < 2) ? bq : (grp < 4 ? bk : bv);
        g_bcat[idx] = (grp & 1) ? 0.0f : b[j];
    }
}

// ---------------- SGEMM: feat = In(NxK) @ g_wcat(KxM) + g_bcat --------------
// 128x128 block tile, BK=8, 256 threads, 8x8 per thread.
__global__ __launch_bounds__(256) void sgemm_feat(const float* __restrict__ Aext,
                                                  int srcsel, int N, int K, int M) {
    const float* A = (srcsel == 0) ? Aext : (srcsel == 1 ? g_x0 : g_h1);
    __shared__ float As[8][128];
    __shared__ float Bs[8][128];
    int bm = blockIdx.y * 128;
    int bn = blockIdx.x * 128;
    int tid = threadIdx.x;
    int tx = tid & 15;   // 0..15 -> 8 cols each
    int ty = tid >> 4;   // 0..15 -> 8 rows each

    float acc[8][8];
#pragma unroll
    for (int i = 0; i < 8; i++)
#pragma unroll
        for (int j = 0; j < 8; j++) acc[i][j] = 0.0f;

    int rowA = tid >> 1;         // 0..127
    int kA = (tid & 1) * 4;      // 0 or 4
    int rowB = tid >> 5;         // 0..7
    int colB = (tid & 31) * 4;   // 0..124
    int garow = bm + rowA;

    for (int k0 = 0; k0 < K; k0 += 8) {
        float4 a4 = make_float4(0.f, 0.f, 0.f, 0.f);
        if (garow < N) a4 = *(const float4*)(A + (size_t)garow * K + k0 + kA);
        As[kA + 0][rowA] = a4.x;
        As[kA + 1][rowA] = a4.y;
        As[kA + 2][rowA] = a4.z;
        As[kA + 3][rowA] = a4.w;
        float4 b4 = *(const float4*)(g_wcat + (size_t)(k0 + rowB) * M + bn + colB);
        *(float4*)(&Bs[rowB][colB]) = b4;
        __syncthreads();
#pragma unroll
        for (int kk = 0; kk < 8; kk++) {
            float ar[8], br[8];
            *(float4*)&ar[0] = *(const float4*)&As[kk][ty * 8];
            *(float4*)&ar[4] = *(const float4*)&As[kk][ty * 8 + 4];
            *(float4*)&br[0] = *(const float4*)&Bs[kk][tx * 8];
            *(float4*)&br[4] = *(const float4*)&Bs[kk][tx * 8 + 4];
#pragma unroll
            for (int i = 0; i < 8; i++)
#pragma unroll
                for (int j = 0; j < 8; j++) acc[i][j] = fmaf(ar[i], br[j], acc[i][j]);
        }
        __syncthreads();
    }
#pragma unroll
    for (int i = 0; i < 8; i++) {
        int r = bm + ty * 8 + i;
        if (r < N) {
#pragma unroll
            for (int j = 0; j < 8; j += 4) {
                int cc = bn + tx * 8 + j;
                float4 o;
                o.x = acc[i][j + 0] + g_bcat[cc + 0];
                o.y = acc[i][j + 1] + g_bcat[cc + 1];
                o.z = acc[i][j + 2] + g_bcat[cc + 2];
                o.w = acc[i][j + 3] + g_bcat[cc + 3];
                *(float4*)(g_feat + (size_t)r * M + cc) = o;
            }
        }
    }
}

// ---------------- zero accumulators -----------------------------------------
__global__ void zero_kernel(int lenAcc) {
    int idx = blockIdx.x * blockDim.x + threadIdx.x;
    if (idx < lenAcc) g_acc[idx] = 0.0f;
    if (idx < NN) g_cnt[idx] = 0.0f;
}

// ---------------- edge kernel: warp per edge ---------------------------------
// q = Aq[dst]+Bq[src]; k = Ak[dst]+Bk[src]; v = (Av[dst]+Bv[src]) * ew
// softmax(q*k*scale) per head (hs = O/8 channels = 4 lanes x CPT), ctx = p*v,
// vector red into g_acc[dst], count into g_cnt[dst].
template <int O>
__global__ __launch_bounds__(256) void edge_kernel(const int* __restrict__ esrc,
                                                   const int* __restrict__ edst, int E) {
    constexpr int CPT = O / 32;          // channels per thread (4 or 2)
    constexpr int ST = 6 * O;            // feat row stride
    const float SCALE = (O == 128) ? 0.25f : 0.3535533905932738f;  // 1/sqrt(O/8)

    int gwarp = (blockIdx.x * blockDim.x + threadIdx.x) >> 5;
    int lane = threadIdx.x & 31;
    if (gwarp >= E) return;

    int s = esrc[gwarp];
    int d = edst[gwarp];
    int dd = abs(d - s);
    float ew = (dd > 8) ? 1.0f : ((dd == 8) ? 0.0f : -1.0f);

    const float* fd = g_feat + (size_t)d * ST;
    const float* fs = g_feat + (size_t)s * ST;
    int c = lane * CPT;

    float qa[CPT], qb[CPT], ka[CPT], kb[CPT], va[CPT], vb[CPT];
    if constexpr (CPT == 4) {
        *(float4*)qa = *(const float4*)(fd + 0 * O + c);
        *(float4*)qb = *(const float4*)(fs + 1 * O + c);
        *(float4*)ka = *(const float4*)(fd + 2 * O + c);
        *(float4*)kb = *(const float4*)(fs + 3 * O + c);
        *(float4*)va = *(const float4*)(fd + 4 * O + c);
        *(float4*)vb = *(const float4*)(fs + 5 * O + c);
    } else {
        *(float2*)qa = *(const float2*)(fd + 0 * O + c);
        *(float2*)qb = *(const float2*)(fs + 1 * O + c);
        *(float2*)ka = *(const float2*)(fd + 2 * O + c);
        *(float2*)kb = *(const float2*)(fs + 3 * O + c);
        *(float2*)va = *(const float2*)(fd + 4 * O + c);
        *(float2*)vb = *(const float2*)(fs + 5 * O + c);
    }

    float z[CPT], v[CPT];
    float m = -1e30f;
#pragma unroll
    for (int i = 0; i < CPT; i++) {
        float q = qa[i] + qb[i];
        float k = ka[i] + kb[i];
        v[i] = (va[i] + vb[i]) * ew;
        z[i] = q * k * SCALE;
        m = fmaxf(m, z[i]);
    }
    // head spans 4 consecutive lanes (4*CPT = hs channels)
    m = fmaxf(m, __shfl_xor_sync(0xFFFFFFFFu, m, 1));
    m = fmaxf(m, __shfl_xor_sync(0xFFFFFFFFu, m, 2));

    float p[CPT];
    float sum = 0.0f;
#pragma unroll
    for (int i = 0; i < CPT; i++) {
        p[i] = __expf(z[i] - m);
        sum += p[i];
    }
    sum += __shfl_xor_sync(0xFFFFFFFFu, sum, 1);
    sum += __shfl_xor_sync(0xFFFFFFFFu, sum, 2);
    float inv = 1.0f / sum;

    float ctx[CPT];
#pragma unroll
    for (int i = 0; i < CPT; i++) ctx[i] = p[i] * inv * v[i];

    float* ap = g_acc + (size_t)d * O + c;
    if constexpr (CPT == 4) {
        asm volatile("red.global.add.v4.f32 [%0], {%1, %2, %3, %4};" ::"l"(ap),
                     "f"(ctx[0]), "f"(ctx[1]), "f"(ctx[2]), "f"(ctx[3])
                     : "memory");
    } else {
        asm volatile("red.global.add.v2.f32 [%0], {%1, %2};" ::"l"(ap), "f"(ctx[0]),
                     "f"(ctx[1])
                     : "memory");
    }
    if (lane == 0) atomicAdd(&g_cnt[d], 1.0f);
}

// ---------------- finalize: mean, (residual), relu ---------------------------
// mode 0: g_x0 = relu(acc/max(cnt,1))
// mode 1: g_h1 = relu(acc/max(cnt,1))
// mode 2: out  = relu(acc/max(cnt,1) + g_x0)
__global__ void finalize_kernel(float* __restrict__ outp, int O, int mode) {
    int idx = blockIdx.x * blockDim.x + threadIdx.x;
    int total = NN * O;
    if (idx >= total) return;
    int u = idx / O;
    float vv = g_acc[idx] / fmaxf(g_cnt[u], 1.0f);
    if (mode == 2) vv += g_x0[idx];
    vv = fmaxf(vv, 0.0f);
    if (mode == 0)
        g_x0[idx] = vv;
    else if (mode == 1)
        g_h1[idx] = vv;
    else
        outp[idx] = vv;
}

// ---------------- launch -----------------------------------------------------
extern "C" void kernel_launch(void* const* d_in, const int* in_sizes, int n_in,
                              void* d_out, int out_size) {
    const float* x = (const float*)d_in[0];
    const int* e0 = (const int*)d_in[1];
    const int* e1 = (const int*)d_in[2];
    const int* e2 = (const int*)d_in[3];
    const float* wq0 = (const float*)d_in[5];
    const float* bq0 = (const float*)d_in[6];
    const float* wk0 = (const float*)d_in[7];
    const float* bk0 = (const float*)d_in[8];
    const float* wv0 = (const float*)d_in[9];
    const float* bv0 = (const float*)d_in[10];
    const float* wq1 = (const float*)d_in[11];
    const float* bq1 = (const float*)d_in[12];
    const float* wk1 = (const float*)d_in[13];
    const float* bk1 = (const float*)d_in[14];
    const float* wv1 = (const float*)d_in[15];
    const float* bv1 = (const float*)d_in[16];
    const float* wq2 = (const float*)d_in[17];
    const float* bq2 = (const float*)d_in[18];
    const float* wk2 = (const float*)d_in[19];
    const float* bk2 = (const float*)d_in[20];
    const float* wv2 = (const float*)d_in[21];
    const float* bv2 = (const float*)d_in[22];

    int E0 = in_sizes[1] / 2;
    int E1 = in_sizes[2] / 2;
    int E2 = in_sizes[3] / 2;

    dim3 gemmBlk(256);
    int finGrid128 = (NN * 128 + 255) / 256;
    int finGrid64 = (NN * 64 + 255) / 256;

    // ---- Layer 0: C=128, O=128 ----
    build_wcat<<<(128 * 768 + 255) / 256, 256>>>(wq0, wk0, wv0, bq0, bk0, bv0, 128, 128);
    sgemm_feat<<<dim3(768 / 128, (NN + 127) / 128), gemmBlk>>>(x, 0, NN, 128, 768);
    zero_kernel<<<finGrid128, 256>>>(NN * 128);
    edge_kernel<128><<<(E0 + 7) / 8, 256>>>(e0, e0 + E0, E0);
    finalize_kernel<<<finGrid128, 256>>>(nullptr, 128, 0);

    // ---- Layer 1: C=128, O=64 ----
    build_wcat<<<(128 * 384 + 255) / 256, 256>>>(wq1, wk1, wv1, bq1, bk1, bv1, 128, 64);
    sgemm_feat<<<dim3(384 / 128, (NN + 127) / 128), gemmBlk>>>(nullptr, 1, NN, 128, 384);
    zero_kernel<<<finGrid128, 256>>>(NN * 64);
    edge_kernel<64><<<(E1 + 7) / 8, 256>>>(e1, e1 + E1, E1);
    finalize_kernel<<<finGrid64, 256>>>(nullptr, 64, 1);

    // ---- Layer 2: C=64, O=128 ----
    build_wcat<<<(64 * 768 + 255) / 256, 256>>>(wq2, wk2, wv2, bq2, bk2, bv2, 64, 128);
    sgemm_feat<<<dim3(768 / 128, (NN + 127) / 128), gemmBlk>>>(nullptr, 2, NN, 64, 768);
    zero_kernel<<<finGrid128, 256>>>(NN * 128);
    edge_kernel<128><<<(E2 + 7) / 8, 256>>>(e2, e2 + E2, E2);
    finalize_kernel<<<finGrid128, 256>>>((float*)d_out, 128, 2);
}

// round 3
// speedup vs baseline: 1.3905x; 1.3905x over previous
#include <cuda_runtime.h>
#include <math.h>
#include <stdint.h>

#define NN 50000

// ---------------- scratch (device globals; no allocations allowed) ----------
__device__ float g_feat[NN * 768];    // per-node [Aq|Bq|Ak|Bk|Av|Bv], stride 6*O
__device__ float g_x0[NN * 128];      // relu(layer0 out), tf32-rounded (residual + L1 input)
__device__ float g_h1[NN * 64];       // relu(layer1 out), tf32-rounded (L2 input)
__device__ float g_xr[NN * 128];      // tf32-rounded copy of input x (L0 GEMM input)
__device__ float g_acc[NN * 128];     // edge-aggregation accumulator
__device__ float g_cnt[NN];           // edge count per dst
__device__ float g_wcatT[768 * 128];  // transposed transformed weights [M][K], tf32-rounded
__device__ float g_bcat[768];         // concatenated bias (bias only on A columns)

__device__ __forceinline__ float rna_tf32(float v) {
    float o;
    asm("cvt.rna.tf32.f32 %0, %1;" : "=f"(o) : "f"(v));
    return o;
}

// ---------------- build W_catT[col][c] = rna([Wtop-Wbot | Wbot]) ------------
__global__ void build_wcat(const float* __restrict__ wq, const float* __restrict__ wk,
                           const float* __restrict__ wv, const float* __restrict__ bq,
                           const float* __restrict__ bk, const float* __restrict__ bv,
                           int C, int O) {
    int M = 6 * O;
    int idx = blockIdx.x * blockDim.x + threadIdx.x;
    if (idx < C * M) {
        int c = idx / M, col = idx % M;
        int grp = col / O, j = col % O;
        const float* w = (grp < 2) ? wq : (grp < 4 ? wk : wv);
        float top = w[c * O + j];
        float bot = w[(C + c) * O + j];
        float val = (grp & 1) ? bot : (top - bot);
        g_wcatT[(size_t)col * C + c] = rna_tf32(val);
    }
    if (idx < M) {
        int grp = idx / O, j = idx % O;
        const float* b = (grp < 2) ? bq : (grp < 4 ? bk : bv);
        g_bcat[idx] = (grp & 1) ? 0.0f : b[j];
    }
}

// ---------------- round input x to tf32 --------------------------------------
__global__ void round_x_kernel(const float* __restrict__ x, int n) {
    int idx = blockIdx.x * blockDim.x + threadIdx.x;
    if (idx < n) g_xr[idx] = rna_tf32(x[idx]);
}

// ---------------- tf32 tensor-core GEMM: g_feat = A(NxK) @ g_wcatT^T + bias --
// A row-major (stride K), B = g_wcatT row-major [M][K] (i.e. B^T), out stride M.
// 128x128 CTA tile, BK=16, 8 warps of 64x32, mma.m16n8k8.tf32, cp.async dbuf.
// srcsel: 1 -> g_x0, 2 -> g_h1, 3 -> g_xr (device globals resolved IN KERNEL)
template <int K>
__global__ __launch_bounds__(256, 2) void mma_gemm(int srcsel, int N, int M) {
    const float* A = (srcsel == 1) ? g_x0 : ((srcsel == 2) ? g_h1 : g_xr);
    constexpr int PAD = 20;  // floats per row (16 + 4 pad) -> 80B, 16B-aligned
    __shared__ float As[2][128 * PAD];
    __shared__ float Bs[2][128 * PAD];

    const int tid = threadIdx.x;
    const int lane = tid & 31;
    const int wid = tid >> 5;
    const int wm = (wid & 1) * 64;
    const int wn = (wid >> 1) * 32;
    const int bm = blockIdx.y * 128;
    const int bn = blockIdx.x * 128;

    float acc[4][4][4];
#pragma unroll
    for (int a = 0; a < 4; a++)
#pragma unroll
        for (int b = 0; b < 4; b++)
#pragma unroll
            for (int c = 0; c < 4; c++) acc[a][b][c] = 0.0f;

    const int r_ld = tid >> 1;
    const int ch0 = (tid & 1) * 2;
    const int garow = bm + r_ld;
    const float* aptr = A + (size_t)(garow < N ? garow : 0) * K;
    const int asz = (garow < N) ? 16 : 0;
    const float* bptr = g_wcatT + (size_t)(bn + r_ld) * K;

#define SMADDR(p) ((uint32_t)__cvta_generic_to_shared(p))

#define LOAD_STAGE(buf, k0)                                                          \
    {                                                                                \
        _Pragma("unroll") for (int i = 0; i < 2; i++) {                              \
            int ch = ch0 + i;                                                        \
            asm volatile("cp.async.cg.shared.global [%0], [%1], 16, %2;" ::"r"(      \
                             SMADDR(&As[buf][r_ld * PAD + ch * 4])),                 \
                         "l"(aptr + (k0) + ch * 4), "r"(asz));                       \
            asm volatile("cp.async.cg.shared.global [%0], [%1], 16;" ::"r"(          \
                             SMADDR(&Bs[buf][r_ld * PAD + ch * 4])),                 \
                         "l"(bptr + (k0) + ch * 4));                                 \
        }                                                                            \
        asm volatile("cp.async.commit_group;");                                      \
    }

    LOAD_STAGE(0, 0);
    constexpr int NIT = K / 16;
#pragma unroll
    for (int it = 0; it < NIT; it++) {
        const int buf = it & 1;
        if (it + 1 < NIT) {
            LOAD_STAGE(buf ^ 1, (it + 1) * 16);
            asm volatile("cp.async.wait_group 1;");
        } else {
            asm volatile("cp.async.wait_group 0;");
        }
        __syncthreads();

#pragma unroll
        for (int ks = 0; ks < 16; ks += 8) {
            uint32_t af[4][4];
#pragma unroll
            for (int mt = 0; mt < 4; mt++) {
                const float* p = &As[buf][(wm + mt * 16 + (lane & 15)) * PAD + ks +
                                          (lane >> 4) * 4];
                asm volatile(
                    "ldmatrix.sync.aligned.m8n8.x4.shared.b16 {%0,%1,%2,%3}, [%4];"
                    : "=r"(af[mt][0]), "=r"(af[mt][1]), "=r"(af[mt][2]), "=r"(af[mt][3])
                    : "r"(SMADDR(p)));
            }
            uint32_t bf[2][4];
#pragma unroll
            for (int bi = 0; bi < 2; bi++) {
                const float* p = &Bs[buf][(wn + bi * 16 + (lane & 7) +
                                           ((lane >> 4) << 3)) *
                                              PAD +
                                          ks + ((lane >> 3) & 1) * 4];
                asm volatile(
                    "ldmatrix.sync.aligned.m8n8.x4.shared.b16 {%0,%1,%2,%3}, [%4];"
                    : "=r"(bf[bi][0]), "=r"(bf[bi][1]), "=r"(bf[bi][2]), "=r"(bf[bi][3])
                    : "r"(SMADDR(p)));
            }
#pragma unroll
            for (int mt = 0; mt < 4; mt++)
#pragma unroll
                for (int nt = 0; nt < 4; nt++) {
                    uint32_t b0 = bf[nt >> 1][(nt & 1) * 2];
                    uint32_t b1 = bf[nt >> 1][(nt & 1) * 2 + 1];
                    asm volatile(
                        "mma.sync.aligned.m16n8k8.row.col.f32.tf32.tf32.f32 "
                        "{%0,%1,%2,%3}, {%4,%5,%6,%7}, {%8,%9}, {%0,%1,%2,%3};"
                        : "+f"(acc[mt][nt][0]), "+f"(acc[mt][nt][1]),
                          "+f"(acc[mt][nt][2]), "+f"(acc[mt][nt][3])
                        : "r"(af[mt][0]), "r"(af[mt][1]), "r"(af[mt][2]),
                          "r"(af[mt][3]), "r"(b0), "r"(b1));
                }
        }
        __syncthreads();
    }

    // Epilogue: add bias, write g_feat
#pragma unroll
    for (int mt = 0; mt < 4; mt++) {
        int r = bm + wm + mt * 16 + (lane >> 2);
#pragma unroll
        for (int half = 0; half < 2; half++) {
            int rr = r + half * 8;
            if (rr < N) {
#pragma unroll
                for (int nt = 0; nt < 4; nt++) {
                    int c = bn + wn + nt * 8 + (lane & 3) * 2;
                    float2 o;
                    o.x = acc[mt][nt][half * 2 + 0] + g_bcat[c];
                    o.y = acc[mt][nt][half * 2 + 1] + g_bcat[c + 1];
                    *(float2*)(g_feat + (size_t)rr * M + c) = o;
                }
            }
        }
    }
#undef LOAD_STAGE
#undef SMADDR
}

// ---------------- zero accumulators -----------------------------------------
__global__ void zero_kernel(int lenAcc) {
    int idx = blockIdx.x * blockDim.x + threadIdx.x;
    if (idx < lenAcc) g_acc[idx] = 0.0f;
    if (idx < NN) g_cnt[idx] = 0.0f;
}

// ---------------- edge kernel: warp per edge ---------------------------------
template <int O>
__global__ __launch_bounds__(256) void edge_kernel(const int* __restrict__ esrc,
                                                   const int* __restrict__ edst, int E) {
    constexpr int CPT = O / 32;
    constexpr int ST = 6 * O;
    const float SCALE = (O == 128) ? 0.25f : 0.3535533905932738f;

    int gwarp = (blockIdx.x * blockDim.x + threadIdx.x) >> 5;
    int lane = threadIdx.x & 31;
    if (gwarp >= E) return;

    int s = esrc[gwarp];
    int d = edst[gwarp];
    int dd = abs(d - s);
    float ew = (dd > 8) ? 1.0f : ((dd == 8) ? 0.0f : -1.0f);

    const float* fd = g_feat + (size_t)d * ST;
    const float* fs = g_feat + (size_t)s * ST;
    int c = lane * CPT;

    float qa[CPT], qb[CPT], ka[CPT], kb[CPT], va[CPT], vb[CPT];
    if constexpr (CPT == 4) {
        *(float4*)qa = *(const float4*)(fd + 0 * O + c);
        *(float4*)qb = *(const float4*)(fs + 1 * O + c);
        *(float4*)ka = *(const float4*)(fd + 2 * O + c);
        *(float4*)kb = *(const float4*)(fs + 3 * O + c);
        *(float4*)va = *(const float4*)(fd + 4 * O + c);
        *(float4*)vb = *(const float4*)(fs + 5 * O + c);
    } else {
        *(float2*)qa = *(const float2*)(fd + 0 * O + c);
        *(float2*)qb = *(const float2*)(fs + 1 * O + c);
        *(float2*)ka = *(const float2*)(fd + 2 * O + c);
        *(float2*)kb = *(const float2*)(fs + 3 * O + c);
        *(float2*)va = *(const float2*)(fd + 4 * O + c);
        *(float2*)vb = *(const float2*)(fs + 5 * O + c);
    }

    float z[CPT], v[CPT];
    float m = -1e30f;
#pragma unroll
    for (int i = 0; i < CPT; i++) {
        float q = qa[i] + qb[i];
        float k = ka[i] + kb[i];
        v[i] = (va[i] + vb[i]) * ew;
        z[i] = q * k * SCALE;
        m = fmaxf(m, z[i]);
    }
    m = fmaxf(m, __shfl_xor_sync(0xFFFFFFFFu, m, 1));
    m = fmaxf(m, __shfl_xor_sync(0xFFFFFFFFu, m, 2));

    float p[CPT];
    float sum = 0.0f;
#pragma unroll
    for (int i = 0; i < CPT; i++) {
        p[i] = __expf(z[i] - m);
        sum += p[i];
    }
    sum += __shfl_xor_sync(0xFFFFFFFFu, sum, 1);
    sum += __shfl_xor_sync(0xFFFFFFFFu, sum, 2);
    float inv = 1.0f / sum;

    float ctx[CPT];
#pragma unroll
    for (int i = 0; i < CPT; i++) ctx[i] = p[i] * inv * v[i];

    float* ap = g_acc + (size_t)d * O + c;
    if constexpr (CPT == 4) {
        asm volatile("red.global.add.v4.f32 [%0], {%1, %2, %3, %4};" ::"l"(ap),
                     "f"(ctx[0]), "f"(ctx[1]), "f"(ctx[2]), "f"(ctx[3])
                     : "memory");
    } else {
        asm volatile("red.global.add.v2.f32 [%0], {%1, %2};" ::"l"(ap), "f"(ctx[0]),
                     "f"(ctx[1])
                     : "memory");
    }
    if (lane == 0) atomicAdd(&g_cnt[d], 1.0f);
}

// ---------------- finalize: mean, (residual), relu ---------------------------
__global__ void finalize_kernel(float* __restrict__ outp, int O, int mode) {
    int idx = blockIdx.x * blockDim.x + threadIdx.x;
    int total = NN * O;
    if (idx >= total) return;
    int u = idx / O;
    float vv = g_acc[idx] / fmaxf(g_cnt[u], 1.0f);
    if (mode == 2) vv += g_x0[idx];
    vv = fmaxf(vv, 0.0f);
    if (mode == 0)
        g_x0[idx] = rna_tf32(vv);
    else if (mode == 1)
        g_h1[idx] = rna_tf32(vv);
    else
        outp[idx] = vv;
}

// ---------------- launch -----------------------------------------------------
extern "C" void kernel_launch(void* const* d_in, const int* in_sizes, int n_in,
                              void* d_out, int out_size) {
    const float* x = (const float*)d_in[0];
    const int* e0 = (const int*)d_in[1];
    const int* e1 = (const int*)d_in[2];
    const int* e2 = (const int*)d_in[3];
    const float* wq0 = (const float*)d_in[5];
    const float* bq0 = (const float*)d_in[6];
    const float* wk0 = (const float*)d_in[7];
    const float* bk0 = (const float*)d_in[8];
    const float* wv0 = (const float*)d_in[9];
    const float* bv0 = (const float*)d_in[10];
    const float* wq1 = (const float*)d_in[11];
    const float* bq1 = (const float*)d_in[12];
    const float* wk1 = (const float*)d_in[13];
    const float* bk1 = (const float*)d_in[14];
    const float* wv1 = (const float*)d_in[15];
    const float* bv1 = (const float*)d_in[16];
    const float* wq2 = (const float*)d_in[17];
    const float* bq2 = (const float*)d_in[18];
    const float* wk2 = (const float*)d_in[19];
    const float* bk2 = (const float*)d_in[20];
    const float* wv2 = (const float*)d_in[21];
    const float* bv2 = (const float*)d_in[22];

    int E0 = in_sizes[1] / 2;
    int E1 = in_sizes[2] / 2;
    int E2 = in_sizes[3] / 2;

    int finGrid128 = (NN * 128 + 255) / 256;
    int finGrid64 = (NN * 64 + 255) / 256;
    int nblk = (NN + 127) / 128;  // 391

    // ---- Layer 0: C=128, O=128 ----
    build_wcat<<<(128 * 768 + 255) / 256, 256>>>(wq0, wk0, wv0, bq0, bk0, bv0, 128, 128);
    round_x_kernel<<<finGrid128, 256>>>(x, NN * 128);
    mma_gemm<128><<<dim3(768 / 128, nblk), 256>>>(3, NN, 768);
    zero_kernel<<<finGrid128, 256>>>(NN * 128);
    edge_kernel<128><<<(E0 + 7) / 8, 256>>>(e0, e0 + E0, E0);
    finalize_kernel<<<finGrid128, 256>>>(nullptr, 128, 0);

    // ---- Layer 1: C=128, O=64 ----
    build_wcat<<<(128 * 384 + 255) / 256, 256>>>(wq1, wk1, wv1, bq1, bk1, bv1, 128, 64);
    mma_gemm<128><<<dim3(384 / 128, nblk), 256>>>(1, NN, 384);
    zero_kernel<<<finGrid128, 256>>>(NN * 64);
    edge_kernel<64><<<(E1 + 7) / 8, 256>>>(e1, e1 + E1, E1);
    finalize_kernel<<<finGrid64, 256>>>(nullptr, 64, 1);

    // ---- Layer 2: C=64, O=128 ----
    build_wcat<<<(64 * 768 + 255) / 256, 256>>>(wq2, wk2, wv2, bq2, bk2, bv2, 64, 128);
    mma_gemm<64><<<dim3(768 / 128, nblk), 256>>>(2, NN, 768);
    zero_kernel<<<finGrid128, 256>>>(NN * 128);
    edge_kernel<128><<<(E2 + 7) / 8, 256>>>(e2, e2 + E2, E2);
    finalize_kernel<<<finGrid128, 256>>>((float*)d_out, 128, 2);
}

// round 4
// speedup vs baseline: 1.7307x; 1.2447x over previous
#include <cuda_runtime.h>
#include <cuda_bf16.h>
#include <math.h>
#include <stdint.h>

#define NN 50000

// ---------------- scratch (device globals; no allocations allowed) ----------
// Per-node feature block, byte layout (stride 16*O bytes):
//   [0       , 2O ) Aq  bf16[O]
//   [2O      , 4O ) Bq  bf16[O]
//   [4O      , 6O ) Ak  bf16[O]
//   [6O      , 8O ) Bk  bf16[O]
//   [8O      ,12O ) Av  f32 [O]
//   [12O     ,16O ) Bv  f32 [O]
__device__ __align__(16) unsigned char g_feat[NN * 2048];
__device__ float g_x0[NN * 128];      // relu(layer0 out) f32 (residual + L1 GEMM input)
__device__ float g_h1[NN * 64];       // relu(layer1 out) f32 (L2 GEMM input)
__device__ float g_acc[NN * 128];     // edge-aggregation accumulator
__device__ float g_cnt[NN];           // edge count per dst
__device__ float g_wcatT[768 * 128];  // transposed transformed weights [M][K], tf32-rounded
__device__ float g_bcat[768];         // concatenated bias (bias only on A columns)

__device__ __forceinline__ float rna_tf32(float v) {
    float o;
    asm("cvt.rna.tf32.f32 %0, %1;" : "=f"(o) : "f"(v));
    return o;
}

// ---------------- build W_catT[col][c] = rna([Wtop-Wbot | Wbot]); zero cnt ---
__global__ void build_wcat(const float* __restrict__ wq, const float* __restrict__ wk,
                           const float* __restrict__ wv, const float* __restrict__ bq,
                           const float* __restrict__ bk, const float* __restrict__ bv,
                           int C, int O) {
    int M = 6 * O;
    int idx = blockIdx.x * blockDim.x + threadIdx.x;
    if (idx < C * M) {
        int c = idx / M, col = idx % M;
        int grp = col / O, j = col % O;
        const float* w = (grp < 2) ? wq : (grp < 4 ? wk : wv);
        float top = w[c * O + j];
        float bot = w[(C + c) * O + j];
        float val = (grp & 1) ? bot : (top - bot);
        g_wcatT[(size_t)col * C + c] = rna_tf32(val);
    }
    if (idx < M) {
        int grp = idx / O, j = idx % O;
        const float* b = (grp < 2) ? bq : (grp < 4 ? bk : bv);
        g_bcat[idx] = (grp & 1) ? 0.0f : b[j];
    }
    if (idx < NN) g_cnt[idx] = 0.0f;  // prepare edge-count for this layer
}

// ---------------- one-time acc zero ------------------------------------------
__global__ void zero_acc(int n) {
    int idx = blockIdx.x * blockDim.x + threadIdx.x;
    if (idx < n) g_acc[idx] = 0.0f;
}

// ---------------- tf32 tensor-core GEMM --------------------------------------
// feat = A(NxK) @ g_wcatT^T + bias, written into the mixed bf16/f32 node layout.
// A fragments are RNA-rounded to tf32 in-register (B pre-rounded in build_wcat).
// srcsel: 0 -> Aext (layer-0 input x), 1 -> g_x0, 2 -> g_h1.
template <int K, int O>
__global__ __launch_bounds__(256, 2) void mma_gemm(const float* __restrict__ Aext,
                                                   int srcsel, int N) {
    constexpr int M = 6 * O;
    const float* A = (srcsel == 0) ? Aext : ((srcsel == 1) ? g_x0 : g_h1);
    constexpr int PAD = 20;
    __shared__ float As[2][128 * PAD];
    __shared__ float Bs[2][128 * PAD];

    const int tid = threadIdx.x;
    const int lane = tid & 31;
    const int wid = tid >> 5;
    const int wm = (wid & 1) * 64;
    const int wn = (wid >> 1) * 32;
    const int bm = blockIdx.y * 128;
    const int bn = blockIdx.x * 128;

    float acc[4][4][4];
#pragma unroll
    for (int a = 0; a < 4; a++)
#pragma unroll
        for (int b = 0; b < 4; b++)
#pragma unroll
            for (int c = 0; c < 4; c++) acc[a][b][c] = 0.0f;

    const int r_ld = tid >> 1;
    const int ch0 = (tid & 1) * 2;
    const int garow = bm + r_ld;
    const float* aptr = A + (size_t)(garow < N ? garow : 0) * K;
    const int asz = (garow < N) ? 16 : 0;
    const float* bptr = g_wcatT + (size_t)(bn + r_ld) * K;

#define SMADDR(p) ((uint32_t)__cvta_generic_to_shared(p))

#define LOAD_STAGE(buf, k0)                                                          \
    {                                                                                \
        _Pragma("unroll") for (int i = 0; i < 2; i++) {                              \
            int ch = ch0 + i;                                                        \
            asm volatile("cp.async.cg.shared.global [%0], [%1], 16, %2;" ::"r"(      \
                             SMADDR(&As[buf][r_ld * PAD + ch * 4])),                 \
                         "l"(aptr + (k0) + ch * 4), "r"(asz));                       \
            asm volatile("cp.async.cg.shared.global [%0], [%1], 16;" ::"r"(          \
                             SMADDR(&Bs[buf][r_ld * PAD + ch * 4])),                 \
                         "l"(bptr + (k0) + ch * 4));                                 \
        }                                                                            \
        asm volatile("cp.async.commit_group;");                                      \
    }

    LOAD_STAGE(0, 0);
    constexpr int NIT = K / 16;
#pragma unroll
    for (int it = 0; it < NIT; it++) {
        const int buf = it & 1;
        if (it + 1 < NIT) {
            LOAD_STAGE(buf ^ 1, (it + 1) * 16);
            asm volatile("cp.async.wait_group 1;");
        } else {
            asm volatile("cp.async.wait_group 0;");
        }
        __syncthreads();

#pragma unroll
        for (int ks = 0; ks < 16; ks += 8) {
            uint32_t af[4][4];
#pragma unroll
            for (int mt = 0; mt < 4; mt++) {
                const float* p = &As[buf][(wm + mt * 16 + (lane & 15)) * PAD + ks +
                                          (lane >> 4) * 4];
                asm volatile(
                    "ldmatrix.sync.aligned.m8n8.x4.shared.b16 {%0,%1,%2,%3}, [%4];"
                    : "=r"(af[mt][0]), "=r"(af[mt][1]), "=r"(af[mt][2]), "=r"(af[mt][3])
                    : "r"(SMADDR(p)));
#pragma unroll
                for (int r = 0; r < 4; r++)
                    af[mt][r] = __float_as_uint(rna_tf32(__uint_as_float(af[mt][r])));
            }
            uint32_t bf[2][4];
#pragma unroll
            for (int bi = 0; bi < 2; bi++) {
                const float* p = &Bs[buf][(wn + bi * 16 + (lane & 7) +
                                           ((lane >> 4) << 3)) *
                                              PAD +
                                          ks + ((lane >> 3) & 1) * 4];
                asm volatile(
                    "ldmatrix.sync.aligned.m8n8.x4.shared.b16 {%0,%1,%2,%3}, [%4];"
                    : "=r"(bf[bi][0]), "=r"(bf[bi][1]), "=r"(bf[bi][2]), "=r"(bf[bi][3])
                    : "r"(SMADDR(p)));
            }
#pragma unroll
            for (int mt = 0; mt < 4; mt++)
#pragma unroll
                for (int nt = 0; nt < 4; nt++) {
                    uint32_t b0 = bf[nt >> 1][(nt & 1) * 2];
                    uint32_t b1 = bf[nt >> 1][(nt & 1) * 2 + 1];
                    asm volatile(
                        "mma.sync.aligned.m16n8k8.row.col.f32.tf32.tf32.f32 "
                        "{%0,%1,%2,%3}, {%4,%5,%6,%7}, {%8,%9}, {%0,%1,%2,%3};"
                        : "+f"(acc[mt][nt][0]), "+f"(acc[mt][nt][1]),
                          "+f"(acc[mt][nt][2]), "+f"(acc[mt][nt][3])
                        : "r"(af[mt][0]), "r"(af[mt][1]), "r"(af[mt][2]),
                          "r"(af[mt][3]), "r"(b0), "r"(b1));
                }
        }
        __syncthreads();
    }

    // Epilogue: add bias, write mixed-precision node layout.
#pragma unroll
    for (int mt = 0; mt < 4; mt++) {
        int r = bm + wm + mt * 16 + (lane >> 2);
#pragma unroll
        for (int half = 0; half < 2; half++) {
            int rr = r + half * 8;
            if (rr < N) {
                unsigned char* base = g_feat + (size_t)rr * (16 * O);
#pragma unroll
                for (int nt = 0; nt < 4; nt++) {
                    int c = bn + wn + nt * 8 + (lane & 3) * 2;
                    int grp = c / O;
                    int j = c - grp * O;
                    float ox = acc[mt][nt][half * 2 + 0] + g_bcat[c];
                    float oy = acc[mt][nt][half * 2 + 1] + g_bcat[c + 1];
                    if (grp < 4) {
                        __nv_bfloat162 h2 = __floats2bfloat162_rn(ox, oy);
                        *(__nv_bfloat162*)(base + grp * (2 * O) + j * 2) = h2;
                    } else {
                        *(float2*)(base + 8 * O + (grp - 4) * (4 * O) + j * 4) =
                            make_float2(ox, oy);
                    }
                }
            }
        }
    }
#undef LOAD_STAGE
#undef SMADDR
}

// ---------------- edge kernel: warp per edge ---------------------------------
__device__ __forceinline__ void bf4_unpack(uint2 u, float* out) {
    float2 a = __bfloat1622float2(*reinterpret_cast<__nv_bfloat162*>(&u.x));
    float2 b = __bfloat1622float2(*reinterpret_cast<__nv_bfloat162*>(&u.y));
    out[0] = a.x;
    out[1] = a.y;
    out[2] = b.x;
    out[3] = b.y;
}
__device__ __forceinline__ void bf2_unpack(uint32_t u, float* out) {
    float2 a = __bfloat1622float2(*reinterpret_cast<__nv_bfloat162*>(&u));
    out[0] = a.x;
    out[1] = a.y;
}

template <int O>
__global__ __launch_bounds__(256) void edge_kernel(const int* __restrict__ esrc,
                                                   const int* __restrict__ edst, int E) {
    constexpr int CPT = O / 32;
    const float SCALE = (O == 128) ? 0.25f : 0.3535533905932738f;

    int gwarp = (blockIdx.x * blockDim.x + threadIdx.x) >> 5;
    int lane = threadIdx.x & 31;
    if (gwarp >= E) return;

    int s = esrc[gwarp];
    int d = edst[gwarp];
    int dd = abs(d - s);
    float ew = (dd > 8) ? 1.0f : ((dd == 8) ? 0.0f : -1.0f);

    const unsigned char* fd = g_feat + (size_t)d * (16 * O);
    const unsigned char* fs = g_feat + (size_t)s * (16 * O);
    int c = lane * CPT;

    float qa[CPT], qb[CPT], ka[CPT], kb[CPT], va[CPT], vb[CPT];
    if constexpr (CPT == 4) {
        bf4_unpack(*(const uint2*)(fd + 0 * O + c * 2), qa);
        bf4_unpack(*(const uint2*)(fs + 2 * O + c * 2), qb);
        bf4_unpack(*(const uint2*)(fd + 4 * O + c * 2), ka);
        bf4_unpack(*(const uint2*)(fs + 6 * O + c * 2), kb);
        *(float4*)va = *(const float4*)(fd + 8 * O + c * 4);
        *(float4*)vb = *(const float4*)(fs + 12 * O + c * 4);
    } else {
        bf2_unpack(*(const uint32_t*)(fd + 0 * O + c * 2), qa);
        bf2_unpack(*(const uint32_t*)(fs + 2 * O + c * 2), qb);
        bf2_unpack(*(const uint32_t*)(fd + 4 * O + c * 2), ka);
        bf2_unpack(*(const uint32_t*)(fs + 6 * O + c * 2), kb);
        *(float2*)va = *(const float2*)(fd + 8 * O + c * 4);
        *(float2*)vb = *(const float2*)(fs + 12 * O + c * 4);
    }

    float z[CPT], v[CPT];
    float m = -1e30f;
#pragma unroll
    for (int i = 0; i < CPT; i++) {
        float q = qa[i] + qb[i];
        float k = ka[i] + kb[i];
        v[i] = (va[i] + vb[i]) * ew;
        z[i] = q * k * SCALE;
        m = fmaxf(m, z[i]);
    }
    m = fmaxf(m, __shfl_xor_sync(0xFFFFFFFFu, m, 1));
    m = fmaxf(m, __shfl_xor_sync(0xFFFFFFFFu, m, 2));

    float p[CPT];
    float sum = 0.0f;
#pragma unroll
    for (int i = 0; i < CPT; i++) {
        p[i] = __expf(z[i] - m);
        sum += p[i];
    }
    sum += __shfl_xor_sync(0xFFFFFFFFu, sum, 1);
    sum += __shfl_xor_sync(0xFFFFFFFFu, sum, 2);
    float inv = 1.0f / sum;

    float ctx[CPT];
#pragma unroll
    for (int i = 0; i < CPT; i++) ctx[i] = p[i] * inv * v[i];

    float* ap = g_acc + (size_t)d * O + c;
    if constexpr (CPT == 4) {
        asm volatile("red.global.add.v4.f32 [%0], {%1, %2, %3, %4};" ::"l"(ap),
                     "f"(ctx[0]), "f"(ctx[1]), "f"(ctx[2]), "f"(ctx[3])
                     : "memory");
    } else {
        asm volatile("red.global.add.v2.f32 [%0], {%1, %2};" ::"l"(ap), "f"(ctx[0]),
                     "f"(ctx[1])
                     : "memory");
    }
    if (lane == 0) atomicAdd(&g_cnt[d], 1.0f);
}

// ---------------- finalize: mean, (residual), relu; zeroes acc ---------------
// mode 0: g_x0 = relu(acc/cnt); mode 1: g_h1 = relu(acc/cnt);
// mode 2: out = relu(acc/cnt + g_x0)
__global__ void finalize_kernel(float* __restrict__ outp, int O, int mode) {
    int idx = blockIdx.x * blockDim.x + threadIdx.x;
    int total = NN * O;
    if (idx >= total) return;
    int u = idx / O;
    float vv = g_acc[idx] / fmaxf(g_cnt[u], 1.0f);
    if (mode != 2) g_acc[idx] = 0.0f;  // re-arm accumulator for next layer
    if (mode == 2) vv += g_x0[idx];
    vv = fmaxf(vv, 0.0f);
    if (mode == 0)
        g_x0[idx] = vv;
    else if (mode == 1)
        g_h1[idx] = vv;
    else
        outp[idx] = vv;
}

// ---------------- launch -----------------------------------------------------
extern "C" void kernel_launch(void* const* d_in, const int* in_sizes, int n_in,
                              void* d_out, int out_size) {
    const float* x = (const float*)d_in[0];
    const int* e0 = (const int*)d_in[1];
    const int* e1 = (const int*)d_in[2];
    const int* e2 = (const int*)d_in[3];
    const float* wq0 = (const float*)d_in[5];
    const float* bq0 = (const float*)d_in[6];
    const float* wk0 = (const float*)d_in[7];
    const float* bk0 = (const float*)d_in[8];
    const float* wv0 = (const float*)d_in[9];
    const float* bv0 = (const float*)d_in[10];
    const float* wq1 = (const float*)d_in[11];
    const float* bq1 = (const float*)d_in[12];
    const float* wk1 = (const float*)d_in[13];
    const float* bk1 = (const float*)d_in[14];
    const float* wv1 = (const float*)d_in[15];
    const float* bv1 = (const float*)d_in[16];
    const float* wq2 = (const float*)d_in[17];
    const float* bq2 = (const float*)d_in[18];
    const float* wk2 = (const float*)d_in[19];
    const float* bk2 = (const float*)d_in[20];
    const float* wv2 = (const float*)d_in[21];
    const float* bv2 = (const float*)d_in[22];

    int E0 = in_sizes[1] / 2;
    int E1 = in_sizes[2] / 2;
    int E2 = in_sizes[3] / 2;

    int finGrid128 = (NN * 128 + 255) / 256;
    int finGrid64 = (NN * 64 + 255) / 256;
    int nblk = (NN + 127) / 128;
    // build_wcat grid must also cover NN threads for the cnt-zero side job
    int bw768 = (128 * 768 + 255) / 256;   // 384 blocks > NN/256 ✓
    int bw384 = (NN * 1 + 255) / 256 > (128 * 384 + 255) / 256
                    ? (NN + 255) / 256
                    : (128 * 384 + 255) / 256;
    int bw468 = (64 * 768 + 255) / 256 > (NN + 255) / 256 ? (64 * 768 + 255) / 256
                                                          : (NN + 255) / 256;

    zero_acc<<<finGrid128, 256>>>(NN * 128);  // one-time; finalize re-arms after

    // ---- Layer 0: C=128, O=128 ----
    build_wcat<<<bw768, 256>>>(wq0, wk0, wv0, bq0, bk0, bv0, 128, 128);
    mma_gemm<128, 128><<<dim3(6, nblk), 256>>>(x, 0, NN);
    edge_kernel<128><<<(E0 + 7) / 8, 256>>>(e0, e0 + E0, E0);
    finalize_kernel<<<finGrid128, 256>>>(nullptr, 128, 0);

    // ---- Layer 1: C=128, O=64 ----
    build_wcat<<<bw384, 256>>>(wq1, wk1, wv1, bq1, bk1, bv1, 128, 64);
    mma_gemm<128, 64><<<dim3(3, nblk), 256>>>(nullptr, 1, NN);
    edge_kernel<64><<<(E1 + 7) / 8, 256>>>(e1, e1 + E1, E1);
    finalize_kernel<<<finGrid64, 256>>>(nullptr, 64, 1);

    // ---- Layer 2: C=64, O=128 ----
    build_wcat<<<bw468, 256>>>(wq2, wk2, wv2, bq2, bk2, bv2, 64, 128);
    mma_gemm<64, 128><<<dim3(6, nblk), 256>>>(nullptr, 2, NN);
    edge_kernel<128><<<(E2 + 7) / 8, 256>>>(e2, e2 + E2, E2);
    finalize_kernel<<<finGrid128, 256>>>((float*)d_out, 128, 2);
}